// round 7
// baseline (speedup 1.0000x reference)
#include <cuda_runtime.h>
#include <cstdint>

// PSRoIPool, warp-per-output: x (4, 1029, 96, 96) fp32, rois (512,5) fp32,
// out (512, 21, 7, 7) fp32.  Flat out idx = k*1029 + r; input channel = r;
// bin i = (r%49)/7, j = r%7.  One warp computes one output: lanes stripe the
// flattened bin window (contiguous addresses -> coalesced sectors), then
// butterfly-reduce.
//
// NUMERIC CONTRACT (verified R5): bin sizes are reciprocal-multiplies
// __fmul_rn(extent, fl(1/7)) — NOT divisions. Do not change.

#define C_TOT   1029
#define PH      7
#define PW      7
#define HH      96
#define WW      96
#define PLANE   (HH*WW)
#define KROIS   512
#define SCALE   0.0625f
#define RCP7    0.1428571492433547973632812500f   // fl(1/7) = 0x3E124925
#define TOTAL   (KROIS * C_TOT)                   // 526848
#define THREADS 256
#define WPB     (THREADS / 32)

__global__ __launch_bounds__(THREADS) void psroi_warp(
    const float* __restrict__ x,
    const float* __restrict__ rois,
    float* __restrict__ out)
{
    const int widx = blockIdx.x * WPB + (threadIdx.x >> 5);   // output index
    const int lane = threadIdx.x & 31;
    if (widx >= TOTAL) return;

    const int k  = widx / C_TOT;
    const int r  = widx - k * C_TOT;
    const int ij = r % (PH * PW);
    const int i  = ij / PW;
    const int j  = ij - i * PW;

    // Warp-uniform roi decode (all lanes load same 5 floats -> broadcast).
    const float* roi = rois + k * 5;
    const int b  = (int)roi[0];
    const int sw = (int)floorf(__fmaf_rn(roi[1], SCALE, 0.5f));
    const int sh = (int)floorf(__fmaf_rn(roi[2], SCALE, 0.5f));
    const int ew = (int)floorf(__fmaf_rn(roi[3], SCALE, 0.5f));
    const int eh = (int)floorf(__fmaf_rn(roi[4], SCALE, 0.5f));

    const float bin_h = __fmul_rn((float)max(eh - sh, 1), RCP7);
    const float bin_w = __fmul_rn((float)max(ew - sw, 1), RCP7);

    const int hs = min(max((int)floorf(__fmul_rn((float)i,       bin_h)) + sh, 0), HH);
    const int he = min(max((int)ceilf (__fmul_rn((float)(i + 1), bin_h)) + sh, 0), HH);
    const int ws = min(max((int)floorf(__fmul_rn((float)j,       bin_w)) + sw, 0), WW);
    const int we = min(max((int)ceilf (__fmul_rn((float)(j + 1), bin_w)) + sw, 0), WW);

    const int wwid = we - ws;
    const int area = (he - hs) * wwid;          // >= 0 always

    float s = 0.0f;
    if (area > 0) {
        const float* __restrict__ win =
            x + ((size_t)b * C_TOT + r) * PLANE + hs * WW + ws;
        // Lanes stripe the flattened window; contiguous e -> contiguous wx.
        for (unsigned e = lane; e < (unsigned)area; e += 32) {
            unsigned hy = e / (unsigned)wwid;
            unsigned wx = e - hy * (unsigned)wwid;
            s += __ldg(win + hy * WW + wx);
        }
    }

    // Warp reduction.
    #pragma unroll
    for (int o = 16; o; o >>= 1)
        s += __shfl_xor_sync(0xffffffffu, s, o);

    if (lane == 0)
        out[widx] = (area > 0) ? __fdiv_rn(s, (float)area) : 0.0f;
}

extern "C" void kernel_launch(void* const* d_in, const int* in_sizes, int n_in,
                              void* d_out, int out_size)
{
    const float* x;
    const float* rois;
    if (n_in >= 2 && in_sizes[0] == KROIS * 5) {
        rois = (const float*)d_in[0];
        x    = (const float*)d_in[1];
    } else {
        x    = (const float*)d_in[0];
        rois = (const float*)d_in[1];
    }
    float* out = (float*)d_out;

    const int blocks = (TOTAL + WPB - 1) / WPB;   // 65856
    psroi_warp<<<blocks, THREADS>>>(x, rois, out);
}

// round 8
// speedup vs baseline: 2.2877x; 2.2877x over previous
#include <cuda_runtime.h>
#include <cstdint>

// PSRoIPool via per-plane smem integral image.
// x (4, 1029, 96, 96) fp32, rois (512,5) fp32, out (512, 21, 7, 7) fp32.
// out[k*1029 + p] pools plane p = c*49+i*7+j of batch b_k over bin (i,j).
// Block per plane p; per batch b: stage plane coalesced -> in-smem 2D prefix
// sum -> each output is a 4-corner gather (no window loops).
//
// NUMERIC CONTRACT (verified R5): bin sizes are reciprocal-multiplies
// __fmul_rn(extent, fl(1/7)) — NOT divisions. Do not change.

#define C_TOT   1029
#define PH      7
#define PW      7
#define HH      96
#define WW      96
#define WP      97            // padded row stride (bank-conflict-free)
#define PLANE   (HH*WW)       // 9216
#define KROIS   512
#define NBATCH  4
#define SCALE   0.0625f
#define RCP7    0.1428571492433547973632812500f   // fl(1/7) = 0x3E124925
#define THREADS 256

__device__ __forceinline__ float corner(const float* __restrict__ S, int a, int b)
{
    return (a > 0 && b > 0) ? S[(a - 1) * WP + (b - 1)] : 0.0f;
}

__global__ __launch_bounds__(THREADS) void psroi_integral(
    const float* __restrict__ x,
    const float* __restrict__ rois,
    float* __restrict__ out)
{
    __shared__ float sp[HH * WP];          // 37248 B
    const int p   = blockIdx.x;            // plane/channel 0..1028
    const int ij  = p % (PH * PW);
    const int i   = ij / PW;
    const int j   = ij - i * PW;
    const int tid = threadIdx.x;

    // Decode this thread's two rois once (k = tid, tid+256).
    int rb[2], rhs[2], rhe[2], rws[2], rwe[2];
    #pragma unroll
    for (int t = 0; t < 2; ++t) {
        const int k = tid + t * THREADS;
        const float* roi = rois + k * 5;
        int b  = (int)roi[0];
        int sw = (int)floorf(__fmaf_rn(roi[1], SCALE, 0.5f));
        int sh = (int)floorf(__fmaf_rn(roi[2], SCALE, 0.5f));
        int ew = (int)floorf(__fmaf_rn(roi[3], SCALE, 0.5f));
        int eh = (int)floorf(__fmaf_rn(roi[4], SCALE, 0.5f));
        float bin_h = __fmul_rn((float)max(eh - sh, 1), RCP7);
        float bin_w = __fmul_rn((float)max(ew - sw, 1), RCP7);
        rb[t]  = b;
        rhs[t] = min(max((int)floorf(__fmul_rn((float)i,       bin_h)) + sh, 0), HH);
        rhe[t] = min(max((int)ceilf (__fmul_rn((float)(i + 1), bin_h)) + sh, 0), HH);
        rws[t] = min(max((int)floorf(__fmul_rn((float)j,       bin_w)) + sw, 0), WW);
        rwe[t] = min(max((int)ceilf (__fmul_rn((float)(j + 1), bin_w)) + sw, 0), WW);
    }

    for (int b = 0; b < NBATCH; ++b) {
        __syncthreads();   // prior pass's gathers done before overwrite
        // Stage plane (b, p): coalesced float4 global loads, scalar smem
        // stores into padded layout (4 elems never cross a row: 96 % 4 == 0).
        const float4* __restrict__ src4 =
            (const float4*)(x + ((size_t)b * C_TOT + p) * PLANE);
        #pragma unroll
        for (int q = 0; q < PLANE / 4 / THREADS; ++q) {      // 9
            const int e   = tid + q * THREADS;               // float4 index
            const float4 v = __ldg(src4 + e);
            const int f   = e * 4;                           // flat float index
            const int row = f / WW;
            const int base = row * WP + (f - row * WW);
            sp[base + 0] = v.x;
            sp[base + 1] = v.y;
            sp[base + 2] = v.z;
            sp[base + 3] = v.w;
        }
        __syncthreads();

        // Row prefix: thread t owns row t (addresses stride 97 across lanes).
        if (tid < HH) {
            float run = 0.0f;
            const int base = tid * WP;
            #pragma unroll 8
            for (int c = 0; c < WW; ++c) { run += sp[base + c]; sp[base + c] = run; }
        }
        __syncthreads();

        // Col prefix: thread t owns column t.
        if (tid < WW) {
            float run = 0.0f;
            #pragma unroll 8
            for (int r2 = 0; r2 < HH; ++r2) {
                run += sp[r2 * WP + tid];
                sp[r2 * WP + tid] = run;
            }
        }
        __syncthreads();

        // Gather: 4-corner difference per roi owned by this thread with b_k==b.
        #pragma unroll
        for (int t = 0; t < 2; ++t) {
            if (rb[t] != b) continue;
            const int k = tid + t * THREADS;
            const int area = (rhe[t] - rhs[t]) * (rwe[t] - rws[t]);
            float val = 0.0f;
            if (area > 0) {
                float bin_sum = corner(sp, rhe[t], rwe[t]) - corner(sp, rhs[t], rwe[t])
                              - corner(sp, rhe[t], rws[t]) + corner(sp, rhs[t], rws[t]);
                val = __fdiv_rn(bin_sum, (float)area);
            }
            out[k * C_TOT + p] = val;
        }
    }
}

extern "C" void kernel_launch(void* const* d_in, const int* in_sizes, int n_in,
                              void* d_out, int out_size)
{
    const float* x;
    const float* rois;
    if (n_in >= 2 && in_sizes[0] == KROIS * 5) {
        rois = (const float*)d_in[0];
        x    = (const float*)d_in[1];
    } else {
        x    = (const float*)d_in[0];
        rois = (const float*)d_in[1];
    }
    float* out = (float*)d_out;

    psroi_integral<<<C_TOT, THREADS>>>(x, rois, out);
}